// round 12
// baseline (speedup 1.0000x reference)
#include <cuda_runtime.h>

static constexpr int Bn   = 128;
static constexpr int Nn   = 256;
static constexpr int SMAX = 300;
static constexpr int JH   = 128;   // j per pair block (half)

typedef unsigned long long u64;

__device__ float    g_partials[Bn];          // per-batch total loss
__device__ float    g_rowhalf[2 * Bn * Nn];  // [h][b][i] row mins over j-half
__device__ float    g_colsum[2 * Bn];        // [2b+h] sum of colmins of half
__device__ float    g_xmean[Bn * SMAX];      // setsize column means
__device__ unsigned g_bcount[Bn];            // per-batch arrivals (4)
__device__ unsigned g_count = 0;             // finisher count (Bn)

__device__ __forceinline__ float fsqrt_ap(float x) {
    float r;
    asm("sqrt.approx.f32 %0, %1;" : "=f"(r) : "f"(x));
    return r;
}
// Warp-wide min for non-negative floats (u32 ordering == float ordering;
// NaN bit patterns are huge, so they lose the min — desired).
__device__ __forceinline__ float warp_min_nonneg(float x) {
    unsigned u = __float_as_uint(x), r;
    asm("redux.sync.min.u32 %0, %1, 0xffffffff;" : "=r"(r) : "r"(u));
    return __uint_as_float(r);
}
// ---- f32x2 packed helpers (Blackwell) ----
__device__ __forceinline__ u64 pack2(float lo, float hi) {
    u64 d;
    asm("mov.b64 %0, {%1, %2};" : "=l"(d) : "f"(lo), "f"(hi));
    return d;
}
__device__ __forceinline__ void unpack2(float& lo, float& hi, u64 v) {
    asm("mov.b64 {%0, %1}, %2;" : "=f"(lo), "=f"(hi) : "l"(v));
}
__device__ __forceinline__ u64 dup2(float x) { return pack2(x, x); }
__device__ __forceinline__ u64 fma2(u64 a, u64 b, u64 c) {
    u64 d;
    asm("fma.rn.f32x2 %0, %1, %2, %3;" : "=l"(d) : "l"(a), "l"(b), "l"(c));
    return d;
}
__device__ __forceinline__ u64 add2(u64 a, u64 b) {
    u64 d;
    asm("add.rn.f32x2 %0, %1, %2;" : "=l"(d) : "l"(a), "l"(b));
    return d;
}

struct PairSmem {
    __align__(16) u64 geo[JH * 10];  // per local j: fx2,fy2,fz2,np2,mx2,my2,mz2,nm2,fe2,pad
    float csum[JH * 15];             // nllc+nllq+fe^2 per (local j, cls*3+chg)
    float colmin[4][JH];             // per row-group column mins (complete rows)
    float rq[2][Nn];                 // per j-quarter row mins (partial: this half)
    float red[8];
};
struct FinSmem {
    float x[SMAX + 4];
    float red[8];
    float redm[8];
    float rede[8];
};
union Smem { PairSmem p; FinSmem f; };

// ---------------------------------------------------------------------------
// grid = 512 x 256 threads, occupancy 4 (6-8 warps/SMSP for latency hiding).
//   bids [0,256):   pair loss, batch b=bid>>1, j-half h=bid&1 (128 j's)
//   bids [256,512): setsize column means, batch b=(bid-256)>>1, col-half
// Per-batch counter (4 arrivals): the 4th finisher combines row-halves,
// col-sums and the setsize softmax; a global counter then emits the scalar.
// ---------------------------------------------------------------------------
__global__ void __launch_bounds__(256, 4) fused_kernel(
    const int*   __restrict__ pcls,  const int*   __restrict__ pchg,
    const int*   __restrict__ n_part,
    const float* __restrict__ cl_logits, const float* __restrict__ ch_logits,
    const float* __restrict__ ppos,  const float* __restrict__ fpos,
    const float* __restrict__ pmom,  const float* __restrict__ fmom,
    const float* __restrict__ pe,    const float* __restrict__ fe,
    const float* __restrict__ pred,
    float* __restrict__ out)
{
    __shared__ Smem     sm;
    __shared__ unsigned s_isfin, s_islast;
    const int t    = threadIdx.x;
    const int lane = t & 31;
    const int w    = t >> 5;

    int b;   // batch this block contributes to

    if (blockIdx.x < 2 * Bn) {
        // ================= PAIR-LOSS BLOCK (batch b, j-half h) =============
        PairSmem& S = sm.p;
        b = blockIdx.x >> 1;
        const int h = blockIdx.x & 1;

        // ---- stage tables for the 128 local j's (split across 256 thr) ----
        if (t < JH) {
            const int jl = t;
            const int gj = b * Nn + h * JH + jl;
            float nc[5], nq[3];
            {
                const float* cl = cl_logits + gj * 5;
                float x0 = cl[0], x1 = cl[1], x2 = cl[2], x3 = cl[3], x4 = cl[4];
                float m  = fmaxf(fmaxf(fmaxf(x0, x1), fmaxf(x2, x3)), x4);
                float s  = __expf(x0 - m) + __expf(x1 - m) + __expf(x2 - m)
                         + __expf(x3 - m) + __expf(x4 - m);
                float lse = m + __logf(s);
                nc[0] = lse - x0; nc[1] = lse - x1; nc[2] = lse - x2;
                nc[3] = lse - x3; nc[4] = lse - x4;
            }
            {
                const float* ch = ch_logits + gj * 3;
                float x0 = ch[0], x1 = ch[1], x2 = ch[2];
                float m  = fmaxf(fmaxf(x0, x1), x2);
                float s  = __expf(x0 - m) + __expf(x1 - m) + __expf(x2 - m);
                float lse = m + __logf(s);
                nq[0] = lse - x0; nq[1] = lse - x1; nq[2] = lse - x2;
            }
            float fev = fe[gj];
            float fe2 = fev * fev;
            #pragma unroll
            for (int c = 0; c < 5; c++)
                #pragma unroll
                for (int q = 0; q < 3; q++)
                    S.csum[jl * 15 + c * 3 + q] = nc[c] + nq[q] + fe2;
        } else {
            const int jl = t - JH;
            const int gj = b * Nn + h * JH + jl;
            float fx = fpos[gj * 3 + 0], fy = fpos[gj * 3 + 1], fz = fpos[gj * 3 + 2];
            float mx = fmom[gj * 3 + 0], my = fmom[gj * 3 + 1], mz = fmom[gj * 3 + 2];
            float fev = fe[gj];
            float np  = fmaf(fx, fx, fmaf(fy, fy, fz * fz));
            float nm  = fmaf(mx, mx, fmaf(my, my, mz * mz));
            u64* g = &S.geo[(size_t)jl * 10];
            g[0] = dup2(fx); g[1] = dup2(fy); g[2] = dup2(fz); g[3] = dup2(np);
            g[4] = dup2(mx); g[5] = dup2(my); g[6] = dup2(mz); g[7] = dup2(nm);
            g[8] = dup2(fev);
        }

        // ---- per-thread: two particle rows (all 256 rows in this block) ----
        const int r   = w & 3;        // row-group: rows [r*64, r*64+64)
        const int q   = w >> 2;       // local j-quarter: [q*64, q*64+64)
        const int i0  = r * 64 + lane;
        const int i1  = i0 + 32;
        const int gi0 = b * Nn + i0;
        const int gi1 = b * Nn + i1;

        const int cc0 = pcls[gi0] * 3 + pchg[gi0];
        const int cc1 = pcls[gi1] * 3 + pchg[gi1];

        float px0 = ppos[gi0*3+0], py0 = ppos[gi0*3+1], pz0 = ppos[gi0*3+2];
        float qx0 = pmom[gi0*3+0], qy0 = pmom[gi0*3+1], qz0 = pmom[gi0*3+2];
        float pe0v = pe[gi0];
        float px1 = ppos[gi1*3+0], py1 = ppos[gi1*3+1], pz1 = ppos[gi1*3+2];
        float qx1 = pmom[gi1*3+0], qy1 = pmom[gi1*3+1], qz1 = pmom[gi1*3+2];
        float pe1v = pe[gi1];

        const u64 m2x2 = pack2(-2.f*px0, -2.f*px1);
        const u64 m2y2 = pack2(-2.f*py0, -2.f*py1);
        const u64 m2z2 = pack2(-2.f*pz0, -2.f*pz1);
        const u64 n2x2 = pack2(-2.f*qx0, -2.f*qx1);
        const u64 n2y2 = pack2(-2.f*qy0, -2.f*qy1);
        const u64 n2z2 = pack2(-2.f*qz0, -2.f*qz1);
        const u64 m2e2 = pack2(-2.f*pe0v, -2.f*pe1v);
        const u64 rp2  = pack2(fmaf(px0, px0, fmaf(py0, py0, pz0 * pz0)),
                               fmaf(px1, px1, fmaf(py1, py1, pz1 * pz1)));
        const u64 rm2v = pack2(fmaf(qx0, qx0, fmaf(qy0, qy0, qz0 * qz0)),
                               fmaf(qx1, qx1, fmaf(qy1, qy1, qz1 * qz1)));
        const u64 pe2q = pack2(pe0v * pe0v, pe1v * pe1v);

        const float* pc0 = S.csum + cc0;
        const float* pc1 = S.csum + cc1;

        __syncthreads();

        // ---- main loop: identical shape to the best-measured R8 loop ----
        float rm0a = 1e30f, rm0b = 1e30f, rm1a = 1e30f, rm1b = 1e30f;
        const int jbase = q * 64;
        #pragma unroll 8
        for (int jj = 0; jj < 64; jj++) {
            const int jl = jbase + jj;
            const u64* g = &S.geo[(size_t)jl * 10];
            ulonglong2 Ga = *reinterpret_cast<const ulonglong2*>(g + 0);
            ulonglong2 Gb = *reinterpret_cast<const ulonglong2*>(g + 2);
            ulonglong2 Gc = *reinterpret_cast<const ulonglong2*>(g + 4);
            ulonglong2 Gd = *reinterpret_cast<const ulonglong2*>(g + 6);
            u64 fe2j = g[8];

            u64 d2p = add2(rp2, Gb.y);
            d2p = fma2(m2x2, Ga.x, d2p);
            d2p = fma2(m2y2, Ga.y, d2p);
            d2p = fma2(m2z2, Gb.x, d2p);
            u64 d2m = add2(rm2v, Gd.y);
            d2m = fma2(n2x2, Gc.x, d2m);
            d2m = fma2(n2y2, Gc.y, d2m);
            d2m = fma2(n2z2, Gd.x, d2m);

            u64 csp = pack2(pc0[jl * 15], pc1[jl * 15]);
            u64 lb  = add2(fma2(m2e2, fe2j, csp), pe2q);

            float dp0, dp1, dm0, dm1, lb0, lb1;
            unpack2(dp0, dp1, d2p);
            unpack2(dm0, dm1, d2m);
            unpack2(lb0, lb1, lb);

            float l0 = lb0 + (fsqrt_ap(dp0) + fsqrt_ap(dm0));
            float l1 = lb1 + (fsqrt_ap(dp1) + fsqrt_ap(dm1));

            if (jj & 1) { rm0b = fminf(rm0b, l0); rm1b = fminf(rm1b, l1); }
            else        { rm0a = fminf(rm0a, l0); rm1a = fminf(rm1a, l1); }

            float cm = warp_min_nonneg(fminf(l0, l1));
            if (lane == 0) S.colmin[r][jl] = cm;
        }
        S.rq[q][i0] = fminf(rm0a, rm0b);
        S.rq[q][i1] = fminf(rm1a, rm1b);
        __syncthreads();

        // ---- partial combine: rowmins (this half) out, colsum (complete) ----
        {
            float rm = fminf(S.rq[0][t], S.rq[1][t]);
            g_rowhalf[((size_t)h * Bn + b) * Nn + t] = rm;
        }
        if (t < JH) {
            float cm = fminf(fminf(S.colmin[0][t], S.colmin[1][t]),
                             fminf(S.colmin[2][t], S.colmin[3][t]));
            #pragma unroll
            for (int o = 16; o; o >>= 1) cm += __shfl_xor_sync(0xffffffffu, cm, o);
            if (lane == 0) S.red[w] = cm;
        }
        __syncthreads();
        if (t == 0) {
            float s = S.red[0] + S.red[1] + S.red[2] + S.red[3];
            g_colsum[2 * b + h] = s;
        }
    } else {
        // ================= SETSIZE BLOCK (batch b, 150 columns) ============
        const int sb = blockIdx.x - 2 * Bn;
        b = sb >> 1;
        const int hh = sb & 1;
        if (t < 150) {
            const int c = hh * 150 + t;
            const float* base = pred + (size_t)b * Nn * SMAX + c;
            float acc0 = 0.f, acc1 = 0.f, acc2 = 0.f, acc3 = 0.f;
            for (int n = 0; n < Nn; n += 32) {
                float v[32];
                #pragma unroll
                for (int k = 0; k < 32; k++)
                    v[k] = base[(size_t)(n + k) * SMAX];
                #pragma unroll
                for (int k = 0; k < 32; k += 4) {
                    acc0 += v[k + 0];
                    acc1 += v[k + 1];
                    acc2 += v[k + 2];
                    acc3 += v[k + 3];
                }
            }
            g_xmean[b * SMAX + c] = ((acc0 + acc1) + (acc2 + acc3)) * (1.f / Nn);
        }
    }

    // ================= PER-BATCH COMPLETION (4 arrivals) =================
    if (t == 0) {
        __threadfence();
        unsigned old = atomicAdd(&g_bcount[b], 1u);
        s_isfin = (old == 3u) ? 1u : 0u;
    }
    __syncthreads();

    if (s_isfin) {
        // 4th finisher for batch b: combine everything for this batch.
        FinSmem& F = sm.f;
        volatile float* vrh = g_rowhalf;
        volatile float* vxm = g_xmean;
        volatile float* vcs = g_colsum;

        // setsize means into smem (cols t and t+256)
        float a1 = vxm[b * SMAX + t];
        const bool two = (t + 256) < SMAX;
        float a2 = two ? vxm[b * SMAX + t + 256] : -1e30f;
        F.x[t] = a1;
        if (two) F.x[t + 256] = a2;

        // pair: row min across halves, block-sum
        float rm = fminf(vrh[(size_t)b * Nn + t],
                         vrh[((size_t)Bn + b) * Nn + t]);
        #pragma unroll
        for (int o = 16; o; o >>= 1) rm += __shfl_xor_sync(0xffffffffu, rm, o);
        if (lane == 0) F.red[w] = rm;

        // setsize max
        float mv = fmaxf(a1, a2);
        #pragma unroll
        for (int o = 16; o; o >>= 1) mv = fmaxf(mv, __shfl_xor_sync(0xffffffffu, mv, o));
        if (lane == 0) F.redm[w] = mv;
        __syncthreads();

        float m = F.redm[0];
        #pragma unroll
        for (int wv = 1; wv < 8; wv++) m = fmaxf(m, F.redm[wv]);
        float e = __expf(a1 - m) + (two ? __expf(a2 - m) : 0.f);
        #pragma unroll
        for (int o = 16; o; o >>= 1) e += __shfl_xor_sync(0xffffffffu, e, o);
        if (lane == 0) F.rede[w] = e;
        __syncthreads();

        if (t == 0) {
            float rowsum = 0.f, Z = 0.f;
            #pragma unroll
            for (int wv = 0; wv < 8; wv++) { rowsum += F.red[wv]; Z += F.rede[wv]; }
            float pair = rowsum + vcs[2 * b] + vcs[2 * b + 1];
            float logZ = m + __logf(Z);
            float setl = logZ - F.x[n_part[b]];
            g_partials[b] = pair + setl;
            g_bcount[b] = 0;              // reset for next replay
            __threadfence();
            unsigned old2 = atomicAdd(&g_count, 1u);
            s_islast = (old2 == (unsigned)Bn - 1u) ? 1u : 0u;
        }
        __syncthreads();

        if (s_islast) {
            float v = (t < Bn) ? ((volatile float*)g_partials)[t] : 0.f;
            #pragma unroll
            for (int o = 16; o; o >>= 1) v += __shfl_xor_sync(0xffffffffu, v, o);
            if (lane == 0) F.red[w] = v;
            __syncthreads();
            if (t == 0) {
                float s = 0.f;
                #pragma unroll
                for (int wv = 0; wv < 8; wv++) s += F.red[wv];
                out[0] = s * (1.0f / Bn);
                g_count = 0;              // reset for next replay
            }
        }
    }
}

extern "C" void kernel_launch(void* const* d_in, const int* in_sizes, int n_in,
                              void* d_out, int out_size)
{
    const int*   pcls  = (const int*)  d_in[0];
    const int*   pchg  = (const int*)  d_in[1];
    const int*   npart = (const int*)  d_in[2];
    const float* cl    = (const float*)d_in[3];
    const float* ch    = (const float*)d_in[4];
    const float* ppos  = (const float*)d_in[5];
    const float* fpos  = (const float*)d_in[6];
    const float* pmom  = (const float*)d_in[7];
    const float* fmom  = (const float*)d_in[8];
    const float* pe    = (const float*)d_in[9];
    const float* fe    = (const float*)d_in[10];
    const float* pred  = (const float*)d_in[11];

    fused_kernel<<<4 * Bn, 256>>>(pcls, pchg, npart, cl, ch,
                                  ppos, fpos, pmom, fmom, pe, fe, pred,
                                  (float*)d_out);
}

// round 13
// speedup vs baseline: 1.3321x; 1.3321x over previous
#include <cuda_runtime.h>

static constexpr int Bn   = 128;
static constexpr int Nn   = 256;
static constexpr int SMAX = 300;

typedef unsigned long long u64;

__device__ float    g_partials[2 * Bn];  // [0..Bn) pair, [Bn..2Bn) setsize
__device__ unsigned g_count = 0;

__device__ __forceinline__ float fsqrt_ap(float x) {
    float r;
    asm("sqrt.approx.f32 %0, %1;" : "=f"(r) : "f"(x));
    return r;
}
// Warp-wide min for non-negative floats (u32 ordering == float ordering;
// NaN bit patterns are huge, so they lose the min — desired).
__device__ __forceinline__ float warp_min_nonneg(float x) {
    unsigned u = __float_as_uint(x), r;
    asm("redux.sync.min.u32 %0, %1, 0xffffffff;" : "=r"(r) : "r"(u));
    return __uint_as_float(r);
}
// ---- f32x2 packed helpers (Blackwell) ----
__device__ __forceinline__ u64 pack2(float lo, float hi) {
    u64 d;
    asm("mov.b64 %0, {%1, %2};" : "=l"(d) : "f"(lo), "f"(hi));
    return d;
}
__device__ __forceinline__ void unpack2(float& lo, float& hi, u64 v) {
    asm("mov.b64 {%0, %1}, %2;" : "=f"(lo), "=f"(hi) : "l"(v));
}
__device__ __forceinline__ u64 dup2(float x) { return pack2(x, x); }
__device__ __forceinline__ u64 fma2(u64 a, u64 b, u64 c) {
    u64 d;
    asm("fma.rn.f32x2 %0, %1, %2, %3;" : "=l"(d) : "l"(a), "l"(b), "l"(c));
    return d;
}
__device__ __forceinline__ u64 add2(u64 a, u64 b) {
    u64 d;
    asm("add.rn.f32x2 %0, %1, %2;" : "=l"(d) : "l"(a), "l"(b));
    return d;
}

struct PairSmem {
    u64   geo[Nn * 10];     // per j (80B): fx2,fy2,fz2,np2, mx2,my2,mz2,nm2, fe2, pad
    float csum[Nn * 15];    // nllc[c]+nllq[q]+fe^2 per (j, cls*3+chg)
    float colmin[4][Nn];    // per row-group column mins
    float rq[4][Nn];        // per j-quarter row mins
    float red[16];
};
struct SetSmem { float x[SMAX]; float red[16]; };
union FusedSmem { PairSmem p; SetSmem s; };

// ---------------------------------------------------------------------------
// grid = 256 x 512 threads, occupancy 2. blocks [0,128): pair; [128,256): set.
// This is the measured-best R8 structure. Pair: 16 warps = 4 row-groups x
// 4 j-quarters, 2 rows/lane in f32x2, unroll 8 (measured best). Prologue is
// split across all 512 threads (lower half: NLL tables, upper half: geo).
// Setsize: 32-deep MLP column streaming. Last block reduces all partials.
// ---------------------------------------------------------------------------
__global__ void __launch_bounds__(512, 2) fused_kernel(
    const int*   __restrict__ pcls,  const int*   __restrict__ pchg,
    const int*   __restrict__ n_part,
    const float* __restrict__ cl_logits, const float* __restrict__ ch_logits,
    const float* __restrict__ ppos,  const float* __restrict__ fpos,
    const float* __restrict__ pmom,  const float* __restrict__ fmom,
    const float* __restrict__ pe,    const float* __restrict__ fe,
    const float* __restrict__ pred,
    float* __restrict__ out)
{
    __shared__ FusedSmem sm;
    __shared__ unsigned  s_islast;
    __shared__ float     s_fin[8];
    const int t    = threadIdx.x;
    const int lane = t & 31;
    const int w    = t >> 5;

    if (blockIdx.x < Bn) {
        // ================= PAIR-LOSS BLOCK =================
        PairSmem& S = sm.p;
        const int b = blockIdx.x;

        // ---- prologue split across all 512 threads ----
        if (t < Nn) {
            // lower half: NLL tables for pflow j = t
            const int j  = t;
            const int gj = b * Nn + j;
            float nc[5], nq[3];
            {
                const float* cl = cl_logits + gj * 5;
                float x0 = cl[0], x1 = cl[1], x2 = cl[2], x3 = cl[3], x4 = cl[4];
                float m  = fmaxf(fmaxf(fmaxf(x0, x1), fmaxf(x2, x3)), x4);
                float s  = __expf(x0 - m) + __expf(x1 - m) + __expf(x2 - m)
                         + __expf(x3 - m) + __expf(x4 - m);
                float lse = m + __logf(s);
                nc[0] = lse - x0; nc[1] = lse - x1; nc[2] = lse - x2;
                nc[3] = lse - x3; nc[4] = lse - x4;
            }
            {
                const float* ch = ch_logits + gj * 3;
                float x0 = ch[0], x1 = ch[1], x2 = ch[2];
                float m  = fmaxf(fmaxf(x0, x1), x2);
                float s  = __expf(x0 - m) + __expf(x1 - m) + __expf(x2 - m);
                float lse = m + __logf(s);
                nq[0] = lse - x0; nq[1] = lse - x1; nq[2] = lse - x2;
            }
            float fev = fe[gj];
            float fe2 = fev * fev;
            #pragma unroll
            for (int c = 0; c < 5; c++)
                #pragma unroll
                for (int q = 0; q < 3; q++)
                    S.csum[j * 15 + c * 3 + q] = nc[c] + nq[q] + fe2;
        } else {
            // upper half: geometry tables for pflow j = t - 256
            const int j  = t - Nn;
            const int gj = b * Nn + j;
            float fx = fpos[gj * 3 + 0], fy = fpos[gj * 3 + 1], fz = fpos[gj * 3 + 2];
            float mx = fmom[gj * 3 + 0], my = fmom[gj * 3 + 1], mz = fmom[gj * 3 + 2];
            float fev = fe[gj];
            float np  = fmaf(fx, fx, fmaf(fy, fy, fz * fz));
            float nm  = fmaf(mx, mx, fmaf(my, my, mz * mz));
            u64* g = &S.geo[(size_t)j * 10];
            g[0] = dup2(fx); g[1] = dup2(fy); g[2] = dup2(fz); g[3] = dup2(np);
            g[4] = dup2(mx); g[5] = dup2(my); g[6] = dup2(mz); g[7] = dup2(nm);
            g[8] = dup2(fev);
        }

        // ---- per-thread: two particle rows, constants packed f32x2 ----
        const int r   = w & 3;        // row-group: rows [r*64, r*64+64)
        const int q   = w >> 2;       // j-quarter: cols [q*64, q*64+64)
        const int i0  = r * 64 + lane;
        const int i1  = i0 + 32;
        const int gi0 = b * Nn + i0;
        const int gi1 = b * Nn + i1;

        const int cc0 = pcls[gi0] * 3 + pchg[gi0];
        const int cc1 = pcls[gi1] * 3 + pchg[gi1];

        float px0 = ppos[gi0*3+0], py0 = ppos[gi0*3+1], pz0 = ppos[gi0*3+2];
        float qx0 = pmom[gi0*3+0], qy0 = pmom[gi0*3+1], qz0 = pmom[gi0*3+2];
        float pe0v = pe[gi0];
        float px1 = ppos[gi1*3+0], py1 = ppos[gi1*3+1], pz1 = ppos[gi1*3+2];
        float qx1 = pmom[gi1*3+0], qy1 = pmom[gi1*3+1], qz1 = pmom[gi1*3+2];
        float pe1v = pe[gi1];

        const u64 m2x2 = pack2(-2.f*px0, -2.f*px1);
        const u64 m2y2 = pack2(-2.f*py0, -2.f*py1);
        const u64 m2z2 = pack2(-2.f*pz0, -2.f*pz1);
        const u64 n2x2 = pack2(-2.f*qx0, -2.f*qx1);
        const u64 n2y2 = pack2(-2.f*qy0, -2.f*qy1);
        const u64 n2z2 = pack2(-2.f*qz0, -2.f*qz1);
        const u64 m2e2 = pack2(-2.f*pe0v, -2.f*pe1v);
        const u64 rp2  = pack2(fmaf(px0, px0, fmaf(py0, py0, pz0 * pz0)),
                               fmaf(px1, px1, fmaf(py1, py1, pz1 * pz1)));
        const u64 rm2v = pack2(fmaf(qx0, qx0, fmaf(qy0, qy0, qz0 * qz0)),
                               fmaf(qx1, qx1, fmaf(qy1, qy1, qz1 * qz1)));
        const u64 pe2q = pack2(pe0v * pe0v, pe1v * pe1v);

        const float* pc0 = S.csum + cc0;
        const float* pc1 = S.csum + cc1;

        __syncthreads();

        // ---- main loop: measured-best R8 shape (unroll 8) ----
        float rm0a = 1e30f, rm0b = 1e30f, rm1a = 1e30f, rm1b = 1e30f;
        const int jbase = q * 64;
        #pragma unroll 8
        for (int jj = 0; jj < 64; jj++) {
            const int j = jbase + jj;
            const u64* g = &S.geo[(size_t)j * 10];
            ulonglong2 Ga = *reinterpret_cast<const ulonglong2*>(g + 0); // fx2, fy2
            ulonglong2 Gb = *reinterpret_cast<const ulonglong2*>(g + 2); // fz2, np2
            ulonglong2 Gc = *reinterpret_cast<const ulonglong2*>(g + 4); // mx2, my2
            ulonglong2 Gd = *reinterpret_cast<const ulonglong2*>(g + 6); // mz2, nm2
            u64 fe2j = g[8];

            u64 d2p = add2(rp2, Gb.y);
            d2p = fma2(m2x2, Ga.x, d2p);
            d2p = fma2(m2y2, Ga.y, d2p);
            d2p = fma2(m2z2, Gb.x, d2p);
            u64 d2m = add2(rm2v, Gd.y);
            d2m = fma2(n2x2, Gc.x, d2m);
            d2m = fma2(n2y2, Gc.y, d2m);
            d2m = fma2(n2z2, Gd.x, d2m);

            u64 csp = pack2(pc0[j * 15], pc1[j * 15]);
            u64 lb  = add2(fma2(m2e2, fe2j, csp), pe2q);

            float dp0, dp1, dm0, dm1, lb0, lb1;
            unpack2(dp0, dp1, d2p);
            unpack2(dm0, dm1, d2m);
            unpack2(lb0, lb1, lb);

            float l0 = lb0 + (fsqrt_ap(dp0) + fsqrt_ap(dm0));
            float l1 = lb1 + (fsqrt_ap(dp1) + fsqrt_ap(dm1));

            if (jj & 1) { rm0b = fminf(rm0b, l0); rm1b = fminf(rm1b, l1); }
            else        { rm0a = fminf(rm0a, l0); rm1a = fminf(rm1a, l1); }

            float cm = warp_min_nonneg(fminf(l0, l1));
            if (lane == 0) S.colmin[r][j] = cm;
        }
        S.rq[q][i0] = fminf(rm0a, rm0b);
        S.rq[q][i1] = fminf(rm1a, rm1b);
        __syncthreads();

        // ---- combine: sum_i rowmin_i + sum_j colmin_j, block reduce ----
        if (t < Nn) {
            float rm = fminf(fminf(S.rq[0][t], S.rq[1][t]),
                             fminf(S.rq[2][t], S.rq[3][t]));
            float cm = fminf(fminf(S.colmin[0][t], S.colmin[1][t]),
                             fminf(S.colmin[2][t], S.colmin[3][t]));
            float v = rm + cm;
            #pragma unroll
            for (int o = 16; o; o >>= 1) v += __shfl_xor_sync(0xffffffffu, v, o);
            if (lane == 0) S.red[w] = v;
        }
        __syncthreads();
        if (t == 0) {
            float s = 0.f;
            #pragma unroll
            for (int wv = 0; wv < 8; wv++) s += S.red[wv];
            g_partials[b] = s;
        }
    } else {
        // ================= SETSIZE BLOCK (32-deep MLP) =================
        SetSmem& S = sm.s;
        const int b = blockIdx.x - Bn;
        const bool act = t < SMAX;
        const float* base = pred + (size_t)b * Nn * SMAX;

        float a = 0.f;
        if (act) {
            float acc0 = 0.f, acc1 = 0.f, acc2 = 0.f, acc3 = 0.f;
            for (int n = 0; n < Nn; n += 32) {
                float v[32];
                #pragma unroll
                for (int k = 0; k < 32; k++)
                    v[k] = base[(size_t)(n + k) * SMAX + t];
                #pragma unroll
                for (int k = 0; k < 32; k += 4) {
                    acc0 += v[k + 0];
                    acc1 += v[k + 1];
                    acc2 += v[k + 2];
                    acc3 += v[k + 3];
                }
            }
            a = ((acc0 + acc1) + (acc2 + acc3)) * (1.f / Nn);
            S.x[t] = a;
        }

        float v = act ? a : -1e30f;
        #pragma unroll
        for (int o = 16; o; o >>= 1) v = fmaxf(v, __shfl_xor_sync(0xffffffffu, v, o));
        if (lane == 0) S.red[w] = v;
        __syncthreads();
        float m = S.red[0];
        #pragma unroll
        for (int wv = 1; wv < 16; wv++) m = fmaxf(m, S.red[wv]);

        float e = act ? __expf(a - m) : 0.f;
        #pragma unroll
        for (int o = 16; o; o >>= 1) e += __shfl_xor_sync(0xffffffffu, e, o);
        __syncthreads();
        if (lane == 0) S.red[w] = e;
        __syncthreads();

        if (t == 0) {
            float Z = 0.f;
            #pragma unroll
            for (int wv = 0; wv < 16; wv++) Z += S.red[wv];
            float logZ = m + __logf(Z);
            g_partials[Bn + b] = logZ - S.x[n_part[b]];
        }
    }

    // ================= COMPLETION-COUNTER FINAL REDUCTION =================
    if (t == 0) {
        __threadfence();
        unsigned old = atomicAdd(&g_count, 1u);
        s_islast = (old == 2u * Bn - 1u) ? 1u : 0u;
    }
    __syncthreads();
    if (s_islast) {
        if (t < 2 * Bn) {
            float v = ((volatile float*)g_partials)[t];
            #pragma unroll
            for (int o = 16; o; o >>= 1) v += __shfl_xor_sync(0xffffffffu, v, o);
            if (lane == 0) s_fin[w] = v;
        }
        __syncthreads();
        if (t == 0) {
            float s = 0.f;
            #pragma unroll
            for (int wv = 0; wv < 8; wv++) s += s_fin[wv];
            out[0] = s * (1.0f / Bn);
            g_count = 0;   // reset for next graph replay
        }
    }
}

extern "C" void kernel_launch(void* const* d_in, const int* in_sizes, int n_in,
                              void* d_out, int out_size)
{
    const int*   pcls  = (const int*)  d_in[0];
    const int*   pchg  = (const int*)  d_in[1];
    const int*   npart = (const int*)  d_in[2];
    const float* cl    = (const float*)d_in[3];
    const float* ch    = (const float*)d_in[4];
    const float* ppos  = (const float*)d_in[5];
    const float* fpos  = (const float*)d_in[6];
    const float* pmom  = (const float*)d_in[7];
    const float* fmom  = (const float*)d_in[8];
    const float* pe    = (const float*)d_in[9];
    const float* fe    = (const float*)d_in[10];
    const float* pred  = (const float*)d_in[11];

    fused_kernel<<<2 * Bn, 512>>>(pcls, pchg, npart, cl, ch,
                                  ppos, fpos, pmom, fmom, pe, fe, pred,
                                  (float*)d_out);
}